// round 15
// baseline (speedup 1.0000x reference)
#include <cuda_runtime.h>
#include <math.h>

#define TSIG (1 << 20)
#define AL 2000.0f
#define TAU_C 1e-7f
#define TAU2F 1e-14f
#define TOL_C 1e-6
#define NBINS 1024
#define SPITCH 1028
#define SMEM_FFT ((8 * SPITCH + 512) * (int)sizeof(float2))
#define SMEM_OMEGA (NBINS * (int)sizeof(float4))

// Scratch:
// [0,T)  : F (forward FFT of x)
// [T,4T) : FFT work (forward pass1 out; inverse pass1 out, 3 modes)
__device__ float2 g_buf[4 * (size_t)TSIG];
__device__ float4 g_mom[NBINS];      // {M0, M1, M2, fc} per bin
__device__ float  g_csum[NBINS];     // tau * sum_m (isum(fc; w_m) - 1)
__device__ float  g_omega_out[3];

__device__ __forceinline__ float2 cmulf(float2 a, float2 b) {
    return make_float2(a.x * b.x - a.y * b.y, a.x * b.y + a.y * b.x);
}

// ---------------------------------------------------------------------------
// Four-step FFT, N = 1024 x 1024 (unchanged, proven).
// ---------------------------------------------------------------------------

__device__ __forceinline__ void fft1024_shared(float2*& src, float2*& dst,
                                               const float2* tw, int t) {
    #pragma unroll 1
    for (int s = 0; s < 10; s++) {
        int r = 1 << s;
        #pragma unroll
        for (int u = 0; u < 8; u++) {
            int id = u * 256 + t;
            int c  = id >> 9;
            int bf = id & 511;
            int j  = bf >> s;
            float2 a = src[c * SPITCH + bf];
            float2 b = src[c * SPITCH + bf + 512];
            float2 w = tw[j << s];
            int o = bf + ((bf >> s) << s);
            dst[c * SPITCH + o]     = make_float2(a.x + b.x, a.y + b.y);
            float2 d = make_float2(a.x - b.x, a.y - b.y);
            dst[c * SPITCH + o + r] = cmulf(d, w);
        }
        __syncthreads();
        float2* tmp = src; src = dst; dst = tmp;
    }
}

__device__ __forceinline__ void build_tw(float2* tw, int t) {
    for (int m = t; m < 512; m += 256) {
        float s, c;
        sincospif((float)m * (1.0f / 512.0f), &s, &c);
        tw[m] = make_float2(c, -s);
    }
}

// MODE 0: real input x.  MODE 1: conj(u_hat) from closed form.
template <int MODE>
__global__ void __launch_bounds__(256) fft_pass1(const float* rin, float2* out) {
    extern __shared__ float2 sh[];
    float2* bufA = sh;
    float2* bufB = sh + 4 * SPITCH;
    float2* tw   = sh + 8 * SPITCH;
    const int t   = threadIdx.x;
    const int n2b = blockIdx.x * 4;
    const int b   = blockIdx.y;

    build_tw(tw, t);

    float w0 = 0.f, w1 = 0.f, w2 = 0.f;
    const float2* __restrict__ F = g_buf;
    if (MODE == 1) { w0 = g_omega_out[0]; w1 = g_omega_out[1]; w2 = g_omega_out[2]; }
    const float invT = 1.0f / (float)TSIG;

    for (int i = t; i < 4096; i += 256) {
        int n1 = i >> 2, c = i & 3;
        int j = (n1 << 10) + n2b + c;
        float2 v;
        if (MODE == 0) {
            v = make_float2(rin[j], 0.0f);
        } else {
            float f = (float)j * invT;
            if (j >= TSIG / 2) f -= 1.0f;
            float2 Fv = F[j];
            float C  = g_csum[j >> 10];
            float sc = 1.0f - 0.5f * C;          // u = F*(1 - C/2) * i_k
            float rr = Fv.x * sc;
            float ri = Fv.y * sc;
            float d0 = f - w0, d1 = f - w1, d2 = f - w2;
            float b0 = d0 * d0, b1 = d1 * d1, b2 = d2 * d2;
            float sum = (b == 0) ? (b0 + b1) : (b == 1) ? (b0 + b1 + b2) : (b1 + b2);
            float iv = __fdividef(1.0f, fmaf(AL, sum + TAU2F, 1.0f));
            v = make_float2(rr * iv, -(ri * iv));   // conj(u_hat)
        }
        bufA[c * SPITCH + n1] = v;
    }
    __syncthreads();

    float2 *src = bufA, *dst = bufB;
    fft1024_shared(src, dst, tw, t);

    for (int i = t; i < 4096; i += 256) {
        int k1 = i >> 2, c = i & 3;
        int n2 = n2b + c;
        int m = n2 * k1;
        float s, cth;
        sincospif((float)m * (1.0f / 524288.0f), &s, &cth);
        float2 v = src[c * SPITCH + k1];
        out[(size_t)b * TSIG + ((size_t)k1 << 10) + n2] =
            cmulf(v, make_float2(cth, -s));
    }
}

template <int REAL_OUT>
__global__ void __launch_bounds__(256) fft_pass2(const float2* in, float2* cout,
                                                 float* rout) {
    extern __shared__ float2 sh[];
    float2* bufA = sh;
    float2* bufB = sh + 4 * SPITCH;
    float2* tw   = sh + 8 * SPITCH;
    const int t   = threadIdx.x;
    const int k1b = blockIdx.x * 4;
    const int b   = blockIdx.y;

    build_tw(tw, t);
    for (int i = t; i < 4096; i += 256) {
        int c = i >> 10, n2 = i & 1023;
        bufA[c * SPITCH + n2] = in[(size_t)b * TSIG + ((size_t)(k1b + c) << 10) + n2];
    }
    __syncthreads();

    float2 *src = bufA, *dst = bufB;
    fft1024_shared(src, dst, tw, t);

    const float invT = 1.0f / (float)TSIG;
    for (int i = t; i < 4096; i += 256) {
        int k2 = i >> 2, c = i & 3;
        float2 v = src[c * SPITCH + k2];
        size_t o = (size_t)b * TSIG + ((size_t)k2 << 10) + k1b + c;
        if (REAL_OUT) rout[o] = v.x * invT;
        else          cout[o] = v;
    }
}

// ---------------------------------------------------------------------------
// Bin |F|^2 into 1024 bins of 1024 elements: moments M0, M1(=sum P*df),
// M2(=sum P*df^2) about the bin-center frequency fc. One bin per block.
// ---------------------------------------------------------------------------

__global__ void __launch_bounds__(256) bin_moments() {
    __shared__ float sm[8][3];
    const int t = threadIdx.x, blk = blockIdx.x;
    const int lane = t & 31, warp = t >> 5;
    const float invT = 1.0f / (float)TSIG;
    const int j0 = blk << 10;

    const float4* F4 = reinterpret_cast<const float4*>(g_buf + j0);
    float4 a = F4[t * 2];          // elements 4t, 4t+1
    float4 b = F4[t * 2 + 1];      // elements 4t+2, 4t+3
    float P[4];
    P[0] = a.x * a.x + a.y * a.y;
    P[1] = a.z * a.z + a.w * a.w;
    P[2] = b.x * b.x + b.y * b.y;
    P[3] = b.z * b.z + b.w * b.w;

    float dbase = ((float)(4 * t) - 511.5f) * invT;
    float m0 = 0.f, m1 = 0.f, m2 = 0.f;
    #pragma unroll
    for (int e = 0; e < 4; e++) {
        float d = dbase + (float)e * invT;
        m0 += P[e];
        m1 = fmaf(P[e], d, m1);
        m2 = fmaf(P[e] * d, d, m2);
    }
    #pragma unroll
    for (int o = 16; o; o >>= 1) {
        m0 += __shfl_down_sync(0xffffffffu, m0, o);
        m1 += __shfl_down_sync(0xffffffffu, m1, o);
        m2 += __shfl_down_sync(0xffffffffu, m2, o);
    }
    if (lane == 0) { sm[warp][0] = m0; sm[warp][1] = m1; sm[warp][2] = m2; }
    __syncthreads();
    if (t == 0) {
        float M0 = 0.f, M1 = 0.f, M2 = 0.f;
        #pragma unroll
        for (int w = 0; w < 8; w++) { M0 += sm[w][0]; M1 += sm[w][1]; M2 += sm[w][2]; }
        float fc = ((float)j0 + 511.5f) * invT - ((blk >= 512) ? 1.0f : 0.0f);
        g_mom[blk] = make_float4(M0, M1, M2, fc);
    }
}

// ---------------------------------------------------------------------------
// Single-block omega fixed point: 1024 threads, ONE bin per thread.
// 49 updates + %10 checks; accumulates per-bin Csum for the lambda closed form.
// ---------------------------------------------------------------------------

__global__ void __launch_bounds__(1024, 1) vmd_omega(const float* om_init) {
    extern __shared__ float4 Mb[];       // NBINS = 1024
    __shared__ float  sred[32][8];
    __shared__ double dfin[8];
    __shared__ float  sw[4];

    const int tix = threadIdx.x;
    const int lane = tix & 31, warp = tix >> 5;

    Mb[tix] = g_mom[tix];

    float w0 = om_init[0], w1 = om_init[1], w2 = om_init[2];
    float v0 = 0.f, v1 = 0.f, v2 = 0.f;
    float Csum = 0.f;
    __syncthreads();

    const float4 M = Mb[tix];
    const float M0 = M.x, M1 = M.y, M2 = M.z, fc = M.w;

    for (int m = 0; m <= 48; m++) {
        const bool chk = (m > 0) && (m % 10 == 0);
        float acc[8] = {0, 0, 0, 0, 0, 0, 0, 0};
        float isv;

        {
            float d0 = fc - w0, d1 = fc - w1, d2 = fc - w2;
            float b0 = d0 * d0, b1 = d1 * d1, b2 = d2 * d2;
            float D[3], Dp[3];
            const float Dpp[3] = {4.f, 6.f, 4.f};
            D[0] = b0 + b1 + TAU2F; D[1] = D[0] + b2; D[2] = b1 + b2 + TAU2F;
            Dp[0] = 2.f * (d0 + d1); Dp[1] = Dp[0] + 2.f * d2; Dp[2] = 2.f * (d1 + d2);
            float ii[3], u1s[3];
            float is = -1.0f;
            #pragma unroll
            for (int k = 0; k < 3; k++) {
                float i  = __fdividef(1.0f, fmaf(AL, D[k], 1.0f));
                float i2 = i * i, i3 = i2 * i, i4 = i2 * i2;
                float u1 = AL * Dp[k];
                float gp = -2.0f * u1 * i3;
                float h2 = fmaf(3.0f * u1 * u1, i4, -AL * Dpp[k] * i3);
                float T0 = fmaf(M2, h2, fmaf(M1, gp, M0 * i2));
                acc[k]     += T0;
                acc[3 + k] += fmaf(fc, T0, fmaf(M2, gp, M1 * i2));
                ii[k] = i; u1s[k] = u1;
                is += i;
            }
            isv = is;

            if (chk) {
                float e0 = fc - v0, e1 = fc - v1, e2 = fc - v2;
                float c0 = e0 * e0, c1 = e1 * e1, c2 = e2 * e2;
                float Dv[3], Dvp[3];
                Dv[0] = c0 + c1 + TAU2F; Dv[1] = Dv[0] + c2; Dv[2] = c1 + c2 + TAU2F;
                Dvp[0] = 2.f * (e0 + e1); Dvp[1] = Dvp[0] + 2.f * e2; Dvp[2] = 2.f * (e1 + e2);
                #pragma unroll
                for (int k = 0; k < 3; k++) {
                    float iv  = __fdividef(1.0f, fmaf(AL, Dv[k], 1.0f));
                    float iv2 = iv * iv, iv3 = iv2 * iv;
                    float u1v = AL * Dvp[k];
                    float ivp  = -u1v * iv2;
                    float ivpp = fmaf(2.0f * u1v * u1v, iv3, -AL * Dpp[k] * iv2);
                    float i  = ii[k], u1 = u1s[k];
                    float i2 = i * i, i3 = i2 * i;
                    float ip  = -u1 * i2;
                    float ipp = fmaf(2.0f * u1 * u1, i3, -AL * Dpp[k] * i2);
                    float dI = i - iv, dIp = ip - ivp, dIpp = ipp - ivpp;
                    acc[6] += fmaf(M0, dI * dI,
                               fmaf(M1, 2.0f * dI * dIp,
                                    M2 * fmaf(dIp, dIp, dI * dIpp)));
                    acc[7] += fmaf(M0, iv2,
                               fmaf(M1, 2.0f * iv * ivp,
                                    M2 * fmaf(ivp, ivp, iv * ivpp)));
                }
            }
        }

        // warp reduce 8 partials -> sred[32][8]
        #pragma unroll
        for (int a = 0; a < 8; a++) {
            float v = acc[a];
            #pragma unroll
            for (int o = 16; o; o >>= 1) v += __shfl_down_sync(0xffffffffu, v, o);
            if (lane == 0) sred[warp][a] = v;
        }
        __syncthreads();
        // warps 0-7: component = warp, fp64 reduce across the 32 warp-partials
        if (tix < 256) {
            int comp = warp;
            double d = (double)sred[lane][comp];
            #pragma unroll
            for (int o = 16; o; o >>= 1)
                d += __shfl_down_sync(0xffffffffu, d, o);
            if (lane == 0) dfin[comp] = d;
        }
        __syncthreads();
        if (tix == 0) {
            double wn0 = dfin[3] / dfin[0], wn1 = dfin[4] / dfin[1], wn2 = dfin[5] / dfin[2];
            float convf = 0.f;
            if (chk) {
                double udiff = dfin[6] / dfin[7];
                double omd = (fabs(wn0 - wn2) + fabs(wn1 - wn0) + fabs(wn2 - wn1)) * (1.0 / 3.0);
                if (udiff < TOL_C && omd < TOL_C) convf = 1.f;
            }
            sw[0] = (float)wn0; sw[1] = (float)wn1; sw[2] = (float)wn2; sw[3] = convf;
        }
        __syncthreads();

        float nw0 = sw[0], nw1 = sw[1], nw2 = sw[2], cf = sw[3];
        __syncthreads();                 // protect sw before next iteration
        if (cf != 0.f) break;            // frozen: keep w (entering), Csum as-is
        Csum += isv;
        v0 = w0; v1 = w1; v2 = w2;
        w0 = nw0; w1 = nw1; w2 = nw2;
    }

    if (tix == 0) {
        g_omega_out[0] = w0; g_omega_out[1] = w1; g_omega_out[2] = w2;
    }
    g_csum[tix] = TAU_C * Csum;
}

// ---------------------------------------------------------------------------

extern "C" void kernel_launch(void* const* d_in, const int* in_sizes, int n_in,
                              void* d_out, int out_size) {
    const float* x       = (const float*)d_in[0];
    const float* om_init = (const float*)d_in[1];
    float* out = (float*)d_out;

    cudaFuncSetAttribute(fft_pass1<0>, cudaFuncAttributeMaxDynamicSharedMemorySize, SMEM_FFT);
    cudaFuncSetAttribute(fft_pass1<1>, cudaFuncAttributeMaxDynamicSharedMemorySize, SMEM_FFT);
    cudaFuncSetAttribute(fft_pass2<0>, cudaFuncAttributeMaxDynamicSharedMemorySize, SMEM_FFT);
    cudaFuncSetAttribute(fft_pass2<1>, cudaFuncAttributeMaxDynamicSharedMemorySize, SMEM_FFT);
    cudaFuncSetAttribute(vmd_omega,    cudaFuncAttributeMaxDynamicSharedMemorySize, SMEM_OMEGA);

    float2* buf;
    cudaGetSymbolAddress((void**)&buf, g_buf);
    float2* F  = buf;                       // [0, T)
    float2* wk = buf + (size_t)TSIG;        // FFT work region (3T)

    // Forward FFT of x -> F
    fft_pass1<0><<<dim3(256, 1), 256, SMEM_FFT>>>(x, wk);
    fft_pass2<0><<<dim3(256, 1), 256, SMEM_FFT>>>(wk, F, nullptr);

    // Binned moments of |F|^2, then the whole omega fixed point in one block
    bin_moments<<<NBINS, 256>>>();
    vmd_omega<<<1, 1024, SMEM_OMEGA>>>(om_init);

    // inverse: pass1 builds conj(u_hat) from closed form, then Re(fft(conj(u)))/T
    fft_pass1<1><<<dim3(256, 3), 256, SMEM_FFT>>>(nullptr, wk);
    fft_pass2<1><<<dim3(256, 3), 256, SMEM_FFT>>>(wk, nullptr, out);
}

// round 16
// speedup vs baseline: 2.1937x; 2.1937x over previous
#include <cuda_runtime.h>
#include <math.h>

#define TSIG (1 << 20)
#define AL 2000.0f
#define TAU_C 1e-7f
#define TAU2F 1e-14f
#define TOL_C 1e-6
#define NBINS 1024
#define OTPB 128
#define BPT 8                 // bins per thread (NBINS / OTPB)
#define SPITCH 1028
#define SMEM_FFT ((8 * SPITCH + 512) * (int)sizeof(float2))

// Scratch:
// [0,T)  : F (forward FFT of x)
// [T,4T) : FFT work (forward pass1 out; inverse pass1 out, 3 modes)
__device__ float2 g_buf[4 * (size_t)TSIG];
__device__ float4 g_mom[NBINS];      // {M0, M1, M2, fc} per bin
__device__ float  g_csum[NBINS];     // tau * sum_m (isum(fc; w_m) - 1)
__device__ float  g_omega_out[3];

__device__ __forceinline__ float2 cmulf(float2 a, float2 b) {
    return make_float2(a.x * b.x - a.y * b.y, a.x * b.y + a.y * b.x);
}

// ---------------------------------------------------------------------------
// Four-step FFT, N = 1024 x 1024 (unchanged, proven).
// ---------------------------------------------------------------------------

__device__ __forceinline__ void fft1024_shared(float2*& src, float2*& dst,
                                               const float2* tw, int t) {
    #pragma unroll 1
    for (int s = 0; s < 10; s++) {
        int r = 1 << s;
        #pragma unroll
        for (int u = 0; u < 8; u++) {
            int id = u * 256 + t;
            int c  = id >> 9;
            int bf = id & 511;
            int j  = bf >> s;
            float2 a = src[c * SPITCH + bf];
            float2 b = src[c * SPITCH + bf + 512];
            float2 w = tw[j << s];
            int o = bf + ((bf >> s) << s);
            dst[c * SPITCH + o]     = make_float2(a.x + b.x, a.y + b.y);
            float2 d = make_float2(a.x - b.x, a.y - b.y);
            dst[c * SPITCH + o + r] = cmulf(d, w);
        }
        __syncthreads();
        float2* tmp = src; src = dst; dst = tmp;
    }
}

__device__ __forceinline__ void build_tw(float2* tw, int t) {
    for (int m = t; m < 512; m += 256) {
        float s, c;
        sincospif((float)m * (1.0f / 512.0f), &s, &c);
        tw[m] = make_float2(c, -s);
    }
}

// MODE 0: real input x.  MODE 1: conj(u_hat) from closed form.
template <int MODE>
__global__ void __launch_bounds__(256) fft_pass1(const float* rin, float2* out) {
    extern __shared__ float2 sh[];
    float2* bufA = sh;
    float2* bufB = sh + 4 * SPITCH;
    float2* tw   = sh + 8 * SPITCH;
    const int t   = threadIdx.x;
    const int n2b = blockIdx.x * 4;
    const int b   = blockIdx.y;

    build_tw(tw, t);

    float w0 = 0.f, w1 = 0.f, w2 = 0.f;
    const float2* __restrict__ F = g_buf;
    if (MODE == 1) { w0 = g_omega_out[0]; w1 = g_omega_out[1]; w2 = g_omega_out[2]; }
    const float invT = 1.0f / (float)TSIG;

    for (int i = t; i < 4096; i += 256) {
        int n1 = i >> 2, c = i & 3;
        int j = (n1 << 10) + n2b + c;
        float2 v;
        if (MODE == 0) {
            v = make_float2(rin[j], 0.0f);
        } else {
            float f = (float)j * invT;
            if (j >= TSIG / 2) f -= 1.0f;
            float2 Fv = F[j];
            float C  = g_csum[j >> 10];
            float sc = 1.0f - 0.5f * C;          // u = F*(1 - C/2) * i_k
            float rr = Fv.x * sc;
            float ri = Fv.y * sc;
            float d0 = f - w0, d1 = f - w1, d2 = f - w2;
            float b0 = d0 * d0, b1 = d1 * d1, b2 = d2 * d2;
            float sum = (b == 0) ? (b0 + b1) : (b == 1) ? (b0 + b1 + b2) : (b1 + b2);
            float iv = __fdividef(1.0f, fmaf(AL, sum + TAU2F, 1.0f));
            v = make_float2(rr * iv, -(ri * iv));   // conj(u_hat)
        }
        bufA[c * SPITCH + n1] = v;
    }
    __syncthreads();

    float2 *src = bufA, *dst = bufB;
    fft1024_shared(src, dst, tw, t);

    for (int i = t; i < 4096; i += 256) {
        int k1 = i >> 2, c = i & 3;
        int n2 = n2b + c;
        int m = n2 * k1;
        float s, cth;
        sincospif((float)m * (1.0f / 524288.0f), &s, &cth);
        float2 v = src[c * SPITCH + k1];
        out[(size_t)b * TSIG + ((size_t)k1 << 10) + n2] =
            cmulf(v, make_float2(cth, -s));
    }
}

template <int REAL_OUT>
__global__ void __launch_bounds__(256) fft_pass2(const float2* in, float2* cout,
                                                 float* rout) {
    extern __shared__ float2 sh[];
    float2* bufA = sh;
    float2* bufB = sh + 4 * SPITCH;
    float2* tw   = sh + 8 * SPITCH;
    const int t   = threadIdx.x;
    const int k1b = blockIdx.x * 4;
    const int b   = blockIdx.y;

    build_tw(tw, t);
    for (int i = t; i < 4096; i += 256) {
        int c = i >> 10, n2 = i & 1023;
        bufA[c * SPITCH + n2] = in[(size_t)b * TSIG + ((size_t)(k1b + c) << 10) + n2];
    }
    __syncthreads();

    float2 *src = bufA, *dst = bufB;
    fft1024_shared(src, dst, tw, t);

    const float invT = 1.0f / (float)TSIG;
    for (int i = t; i < 4096; i += 256) {
        int k2 = i >> 2, c = i & 3;
        float2 v = src[c * SPITCH + k2];
        size_t o = (size_t)b * TSIG + ((size_t)k2 << 10) + k1b + c;
        if (REAL_OUT) rout[o] = v.x * invT;
        else          cout[o] = v;
    }
}

// ---------------------------------------------------------------------------
// Bin |F|^2 into 1024 bins of 1024 elements (unchanged from R15).
// ---------------------------------------------------------------------------

__global__ void __launch_bounds__(256) bin_moments() {
    __shared__ float sm[8][3];
    const int t = threadIdx.x, blk = blockIdx.x;
    const int lane = t & 31, warp = t >> 5;
    const float invT = 1.0f / (float)TSIG;
    const int j0 = blk << 10;

    const float4* F4 = reinterpret_cast<const float4*>(g_buf + j0);
    float4 a = F4[t * 2];
    float4 b = F4[t * 2 + 1];
    float P[4];
    P[0] = a.x * a.x + a.y * a.y;
    P[1] = a.z * a.z + a.w * a.w;
    P[2] = b.x * b.x + b.y * b.y;
    P[3] = b.z * b.z + b.w * b.w;

    float dbase = ((float)(4 * t) - 511.5f) * invT;
    float m0 = 0.f, m1 = 0.f, m2 = 0.f;
    #pragma unroll
    for (int e = 0; e < 4; e++) {
        float d = dbase + (float)e * invT;
        m0 += P[e];
        m1 = fmaf(P[e], d, m1);
        m2 = fmaf(P[e] * d, d, m2);
    }
    #pragma unroll
    for (int o = 16; o; o >>= 1) {
        m0 += __shfl_down_sync(0xffffffffu, m0, o);
        m1 += __shfl_down_sync(0xffffffffu, m1, o);
        m2 += __shfl_down_sync(0xffffffffu, m2, o);
    }
    if (lane == 0) { sm[warp][0] = m0; sm[warp][1] = m1; sm[warp][2] = m2; }
    __syncthreads();
    if (t == 0) {
        float M0 = 0.f, M1 = 0.f, M2 = 0.f;
        #pragma unroll
        for (int w = 0; w < 8; w++) { M0 += sm[w][0]; M1 += sm[w][1]; M2 += sm[w][2]; }
        float fc = ((float)j0 + 511.5f) * invT - ((blk >= 512) ? 1.0f : 0.0f);
        g_mom[blk] = make_float4(M0, M1, M2, fc);
    }
}

// ---------------------------------------------------------------------------
// Omega fixed point: 128 threads (4 warps), 8 bins per thread, all state in
// registers. Cheap 4-warp barriers; fp64 only in the tiny final tree and the
// 4 convergence checks; fp32 divides for omega (reference is float32).
// ---------------------------------------------------------------------------

__global__ void __launch_bounds__(OTPB, 1) vmd_omega(const float* om_init) {
    __shared__ float sred[4][8];
    __shared__ float sw[4];

    const int tix = threadIdx.x;
    const int lane = tix & 31, warp = tix >> 5;

    float4 M[BPT];
    float  Csum[BPT];
    #pragma unroll
    for (int q = 0; q < BPT; q++) {
        M[q] = g_mom[tix * BPT + q];
        Csum[q] = 0.f;
    }

    float w0 = om_init[0], w1 = om_init[1], w2 = om_init[2];
    float v0 = 0.f, v1 = 0.f, v2 = 0.f;

    for (int m = 0; m <= 48; m++) {
        const bool chk = (m > 0) && (m % 10 == 0);
        float acc[8] = {0, 0, 0, 0, 0, 0, 0, 0};
        float isv[BPT];

        #pragma unroll
        for (int q = 0; q < BPT; q++) {
            const float M0 = M[q].x, M1 = M[q].y, M2 = M[q].z, fc = M[q].w;
            float d0 = fc - w0, d1 = fc - w1, d2 = fc - w2;
            float b0 = d0 * d0, b1 = d1 * d1, b2 = d2 * d2;
            float D[3], Dp[3];
            const float Dpp[3] = {4.f, 6.f, 4.f};
            D[0] = b0 + b1 + TAU2F; D[1] = D[0] + b2; D[2] = b1 + b2 + TAU2F;
            Dp[0] = 2.f * (d0 + d1); Dp[1] = Dp[0] + 2.f * d2; Dp[2] = 2.f * (d1 + d2);
            float ii[3], u1s[3];
            float is = -1.0f;
            #pragma unroll
            for (int k = 0; k < 3; k++) {
                float i  = __fdividef(1.0f, fmaf(AL, D[k], 1.0f));
                float i2 = i * i, i3 = i2 * i, i4 = i2 * i2;
                float u1 = AL * Dp[k];
                float gp = -2.0f * u1 * i3;
                float h2 = fmaf(3.0f * u1 * u1, i4, -AL * Dpp[k] * i3);
                float T0 = fmaf(M2, h2, fmaf(M1, gp, M0 * i2));
                acc[k]     += T0;
                acc[3 + k] += fmaf(fc, T0, fmaf(M2, gp, M1 * i2));
                ii[k] = i; u1s[k] = u1;
                is += i;
            }
            isv[q] = is;

            if (chk) {
                float e0 = fc - v0, e1 = fc - v1, e2 = fc - v2;
                float c0 = e0 * e0, c1 = e1 * e1, c2 = e2 * e2;
                float Dv[3], Dvp[3];
                Dv[0] = c0 + c1 + TAU2F; Dv[1] = Dv[0] + c2; Dv[2] = c1 + c2 + TAU2F;
                Dvp[0] = 2.f * (e0 + e1); Dvp[1] = Dvp[0] + 2.f * e2; Dvp[2] = 2.f * (e1 + e2);
                #pragma unroll
                for (int k = 0; k < 3; k++) {
                    float iv  = __fdividef(1.0f, fmaf(AL, Dv[k], 1.0f));
                    float iv2 = iv * iv, iv3 = iv2 * iv;
                    float u1v = AL * Dvp[k];
                    float ivp  = -u1v * iv2;
                    float ivpp = fmaf(2.0f * u1v * u1v, iv3, -AL * Dpp[k] * iv2);
                    float i  = ii[k], u1 = u1s[k];
                    float i2 = i * i, i3 = i2 * i;
                    float ip  = -u1 * i2;
                    float ipp = fmaf(2.0f * u1 * u1, i3, -AL * Dpp[k] * i2);
                    float dI = i - iv, dIp = ip - ivp, dIpp = ipp - ivpp;
                    acc[6] += fmaf(M0, dI * dI,
                               fmaf(M1, 2.0f * dI * dIp,
                                    M2 * fmaf(dIp, dIp, dI * dIpp)));
                    acc[7] += fmaf(M0, iv2,
                               fmaf(M1, 2.0f * iv * ivp,
                                    M2 * fmaf(ivp, ivp, iv * ivpp)));
                }
            }
        }

        // warp shfl reduce (8 comps), lane0 -> sred[warp][a]
        #pragma unroll
        for (int a = 0; a < 8; a++) {
            float v = acc[a];
            #pragma unroll
            for (int o = 16; o; o >>= 1) v += __shfl_down_sync(0xffffffffu, v, o);
            if (lane == 0) sred[warp][a] = v;
        }
        __syncthreads();

        // warp 0: 32 lanes hold sred[w][a] (w=lane>>3, a=lane&7); fp64 tree
        if (warp == 0) {
            double d = (double)sred[lane >> 3][lane & 7];
            d += __shfl_down_sync(0xffffffffu, d, 16);
            d += __shfl_down_sync(0xffffffffu, d, 8);      // lanes 0..7 = S[a]
            double S[8];
            #pragma unroll
            for (int a = 0; a < 8; a++)
                S[a] = __shfl_sync(0xffffffffu, d, a);
            if (lane == 0) {
                float wn0 = (float)S[3] / (float)S[0];
                float wn1 = (float)S[4] / (float)S[1];
                float wn2 = (float)S[5] / (float)S[2];
                float convf = 0.f;
                if (chk) {
                    double udiff = S[6] / S[7];
                    double omd = (fabs((double)wn0 - (double)wn2) +
                                  fabs((double)wn1 - (double)wn0) +
                                  fabs((double)wn2 - (double)wn1)) * (1.0 / 3.0);
                    if (udiff < TOL_C && omd < TOL_C) convf = 1.f;
                }
                sw[0] = wn0; sw[1] = wn1; sw[2] = wn2; sw[3] = convf;
            }
        }
        __syncthreads();

        float nw0 = sw[0], nw1 = sw[1], nw2 = sw[2], cf = sw[3];
        __syncthreads();                 // protect sw before next iteration
        if (cf != 0.f) break;            // frozen: keep w (entering), Csum as-is
        #pragma unroll
        for (int q = 0; q < BPT; q++) Csum[q] += isv[q];
        v0 = w0; v1 = w1; v2 = w2;
        w0 = nw0; w1 = nw1; w2 = nw2;
    }

    if (tix == 0) {
        g_omega_out[0] = w0; g_omega_out[1] = w1; g_omega_out[2] = w2;
    }
    #pragma unroll
    for (int q = 0; q < BPT; q++)
        g_csum[tix * BPT + q] = TAU_C * Csum[q];
}

// ---------------------------------------------------------------------------

extern "C" void kernel_launch(void* const* d_in, const int* in_sizes, int n_in,
                              void* d_out, int out_size) {
    const float* x       = (const float*)d_in[0];
    const float* om_init = (const float*)d_in[1];
    float* out = (float*)d_out;

    cudaFuncSetAttribute(fft_pass1<0>, cudaFuncAttributeMaxDynamicSharedMemorySize, SMEM_FFT);
    cudaFuncSetAttribute(fft_pass1<1>, cudaFuncAttributeMaxDynamicSharedMemorySize, SMEM_FFT);
    cudaFuncSetAttribute(fft_pass2<0>, cudaFuncAttributeMaxDynamicSharedMemorySize, SMEM_FFT);
    cudaFuncSetAttribute(fft_pass2<1>, cudaFuncAttributeMaxDynamicSharedMemorySize, SMEM_FFT);

    float2* buf;
    cudaGetSymbolAddress((void**)&buf, g_buf);
    float2* F  = buf;                       // [0, T)
    float2* wk = buf + (size_t)TSIG;        // FFT work region (3T)

    // Forward FFT of x -> F
    fft_pass1<0><<<dim3(256, 1), 256, SMEM_FFT>>>(x, wk);
    fft_pass2<0><<<dim3(256, 1), 256, SMEM_FFT>>>(wk, F, nullptr);

    // Binned moments of |F|^2, then the whole omega fixed point in one block
    bin_moments<<<NBINS, 256>>>();
    vmd_omega<<<1, OTPB>>>(om_init);

    // inverse: pass1 builds conj(u_hat) from closed form, then Re(fft(conj(u)))/T
    fft_pass1<1><<<dim3(256, 3), 256, SMEM_FFT>>>(nullptr, wk);
    fft_pass2<1><<<dim3(256, 3), 256, SMEM_FFT>>>(wk, nullptr, out);
}

// round 17
// speedup vs baseline: 2.4507x; 1.1171x over previous
#include <cuda_runtime.h>
#include <math.h>

#define TSIG (1 << 20)
#define AL 2000.0f
#define TAU_C 1e-7f
#define TAU2F 1e-14f
#define TOL_C 1e-6
#define NBINS 256
#define BINSZ 4096            // elements per bin (TSIG / NBINS)
#define OTPB 128
#define BPT 2                 // bins per thread (NBINS / OTPB)
#define SPITCH 1028
#define SMEM_FFT ((8 * SPITCH + 512) * (int)sizeof(float2))

// Scratch:
// [0,T)  : F (forward FFT of x)
// [T,4T) : FFT work (forward pass1 out; inverse pass1 out, 3 modes)
__device__ float2 g_buf[4 * (size_t)TSIG];
__device__ float4 g_mom[NBINS];      // {M0, M1, M2, fc} per bin
__device__ float  g_csum[NBINS];     // tau * sum_m (isum(fc; w_m) - 1)
__device__ float  g_omega_out[3];

__device__ __forceinline__ float2 cmulf(float2 a, float2 b) {
    return make_float2(a.x * b.x - a.y * b.y, a.x * b.y + a.y * b.x);
}

// ---------------------------------------------------------------------------
// Four-step FFT, N = 1024 x 1024 (unchanged, proven).
// ---------------------------------------------------------------------------

__device__ __forceinline__ void fft1024_shared(float2*& src, float2*& dst,
                                               const float2* tw, int t) {
    #pragma unroll 1
    for (int s = 0; s < 10; s++) {
        int r = 1 << s;
        #pragma unroll
        for (int u = 0; u < 8; u++) {
            int id = u * 256 + t;
            int c  = id >> 9;
            int bf = id & 511;
            int j  = bf >> s;
            float2 a = src[c * SPITCH + bf];
            float2 b = src[c * SPITCH + bf + 512];
            float2 w = tw[j << s];
            int o = bf + ((bf >> s) << s);
            dst[c * SPITCH + o]     = make_float2(a.x + b.x, a.y + b.y);
            float2 d = make_float2(a.x - b.x, a.y - b.y);
            dst[c * SPITCH + o + r] = cmulf(d, w);
        }
        __syncthreads();
        float2* tmp = src; src = dst; dst = tmp;
    }
}

__device__ __forceinline__ void build_tw(float2* tw, int t) {
    for (int m = t; m < 512; m += 256) {
        float s, c;
        sincospif((float)m * (1.0f / 512.0f), &s, &c);
        tw[m] = make_float2(c, -s);
    }
}

// MODE 0: real input x.  MODE 1: conj(u_hat) from closed form.
template <int MODE>
__global__ void __launch_bounds__(256) fft_pass1(const float* rin, float2* out) {
    extern __shared__ float2 sh[];
    float2* bufA = sh;
    float2* bufB = sh + 4 * SPITCH;
    float2* tw   = sh + 8 * SPITCH;
    const int t   = threadIdx.x;
    const int n2b = blockIdx.x * 4;
    const int b   = blockIdx.y;

    build_tw(tw, t);

    float w0 = 0.f, w1 = 0.f, w2 = 0.f;
    const float2* __restrict__ F = g_buf;
    if (MODE == 1) { w0 = g_omega_out[0]; w1 = g_omega_out[1]; w2 = g_omega_out[2]; }
    const float invT = 1.0f / (float)TSIG;

    for (int i = t; i < 4096; i += 256) {
        int n1 = i >> 2, c = i & 3;
        int j = (n1 << 10) + n2b + c;
        float2 v;
        if (MODE == 0) {
            v = make_float2(rin[j], 0.0f);
        } else {
            float f = (float)j * invT;
            if (j >= TSIG / 2) f -= 1.0f;
            float2 Fv = F[j];
            float C  = g_csum[j >> 12];
            float sc = 1.0f - 0.5f * C;          // u = F*(1 - C/2) * i_k
            float rr = Fv.x * sc;
            float ri = Fv.y * sc;
            float d0 = f - w0, d1 = f - w1, d2 = f - w2;
            float b0 = d0 * d0, b1 = d1 * d1, b2 = d2 * d2;
            float sum = (b == 0) ? (b0 + b1) : (b == 1) ? (b0 + b1 + b2) : (b1 + b2);
            float iv = __fdividef(1.0f, fmaf(AL, sum + TAU2F, 1.0f));
            v = make_float2(rr * iv, -(ri * iv));   // conj(u_hat)
        }
        bufA[c * SPITCH + n1] = v;
    }
    __syncthreads();

    float2 *src = bufA, *dst = bufB;
    fft1024_shared(src, dst, tw, t);

    for (int i = t; i < 4096; i += 256) {
        int k1 = i >> 2, c = i & 3;
        int n2 = n2b + c;
        int m = n2 * k1;
        float s, cth;
        sincospif((float)m * (1.0f / 524288.0f), &s, &cth);
        float2 v = src[c * SPITCH + k1];
        out[(size_t)b * TSIG + ((size_t)k1 << 10) + n2] =
            cmulf(v, make_float2(cth, -s));
    }
}

template <int REAL_OUT>
__global__ void __launch_bounds__(256) fft_pass2(const float2* in, float2* cout,
                                                 float* rout) {
    extern __shared__ float2 sh[];
    float2* bufA = sh;
    float2* bufB = sh + 4 * SPITCH;
    float2* tw   = sh + 8 * SPITCH;
    const int t   = threadIdx.x;
    const int k1b = blockIdx.x * 4;
    const int b   = blockIdx.y;

    build_tw(tw, t);
    for (int i = t; i < 4096; i += 256) {
        int c = i >> 10, n2 = i & 1023;
        bufA[c * SPITCH + n2] = in[(size_t)b * TSIG + ((size_t)(k1b + c) << 10) + n2];
    }
    __syncthreads();

    float2 *src = bufA, *dst = bufB;
    fft1024_shared(src, dst, tw, t);

    const float invT = 1.0f / (float)TSIG;
    for (int i = t; i < 4096; i += 256) {
        int k2 = i >> 2, c = i & 3;
        float2 v = src[c * SPITCH + k2];
        size_t o = (size_t)b * TSIG + ((size_t)k2 << 10) + k1b + c;
        if (REAL_OUT) rout[o] = v.x * invT;
        else          cout[o] = v;
    }
}

// ---------------------------------------------------------------------------
// Bin |F|^2 into 256 bins of 4096 elements: moments M0, M1(=sum P*df),
// M2(=sum P*df^2) about the bin-center frequency fc. One bin per block.
// ---------------------------------------------------------------------------

__global__ void __launch_bounds__(256) bin_moments() {
    __shared__ float sm[8][3];
    const int t = threadIdx.x, blk = blockIdx.x;
    const int lane = t & 31, warp = t >> 5;
    const float invT = 1.0f / (float)TSIG;
    const int j0 = blk << 12;

    const float4* F4 = reinterpret_cast<const float4*>(g_buf + j0);
    float m0 = 0.f, m1 = 0.f, m2 = 0.f;
    float dbase = ((float)(16 * t) - 2047.5f) * invT;
    #pragma unroll
    for (int e = 0; e < 8; e++) {
        float4 a = F4[t * 8 + e];            // complex elements 16t+2e, +1
        float P0 = a.x * a.x + a.y * a.y;
        float P1 = a.z * a.z + a.w * a.w;
        float d0 = dbase + (float)(2 * e) * invT;
        float d1 = d0 + invT;
        m0 += P0 + P1;
        m1 = fmaf(P0, d0, fmaf(P1, d1, m1));
        m2 = fmaf(P0 * d0, d0, fmaf(P1 * d1, d1, m2));
    }
    #pragma unroll
    for (int o = 16; o; o >>= 1) {
        m0 += __shfl_down_sync(0xffffffffu, m0, o);
        m1 += __shfl_down_sync(0xffffffffu, m1, o);
        m2 += __shfl_down_sync(0xffffffffu, m2, o);
    }
    if (lane == 0) { sm[warp][0] = m0; sm[warp][1] = m1; sm[warp][2] = m2; }
    __syncthreads();
    if (t == 0) {
        float M0 = 0.f, M1 = 0.f, M2 = 0.f;
        #pragma unroll
        for (int w = 0; w < 8; w++) { M0 += sm[w][0]; M1 += sm[w][1]; M2 += sm[w][2]; }
        float fc = ((float)j0 + 2047.5f) * invT - ((blk >= NBINS / 2) ? 1.0f : 0.0f);
        g_mom[blk] = make_float4(M0, M1, M2, fc);
    }
}

// ---------------------------------------------------------------------------
// Omega fixed point: 128 threads (4 warps), 2 bins per thread, all state in
// registers. Cheap 4-warp barriers; tiny fp64 tree for the final sums.
// ---------------------------------------------------------------------------

__global__ void __launch_bounds__(OTPB, 1) vmd_omega(const float* om_init) {
    __shared__ float sred[4][8];
    __shared__ float sw[4];

    const int tix = threadIdx.x;
    const int lane = tix & 31, warp = tix >> 5;

    float4 M[BPT];
    float  Csum[BPT];
    #pragma unroll
    for (int q = 0; q < BPT; q++) {
        M[q] = g_mom[tix * BPT + q];
        Csum[q] = 0.f;
    }

    float w0 = om_init[0], w1 = om_init[1], w2 = om_init[2];
    float v0 = 0.f, v1 = 0.f, v2 = 0.f;

    for (int m = 0; m <= 48; m++) {
        const bool chk = (m > 0) && (m % 10 == 0);
        float acc[8] = {0, 0, 0, 0, 0, 0, 0, 0};
        float isv[BPT];

        #pragma unroll
        for (int q = 0; q < BPT; q++) {
            const float M0 = M[q].x, M1 = M[q].y, M2 = M[q].z, fc = M[q].w;
            float d0 = fc - w0, d1 = fc - w1, d2 = fc - w2;
            float b0 = d0 * d0, b1 = d1 * d1, b2 = d2 * d2;
            float D[3], Dp[3];
            const float Dpp[3] = {4.f, 6.f, 4.f};
            D[0] = b0 + b1 + TAU2F; D[1] = D[0] + b2; D[2] = b1 + b2 + TAU2F;
            Dp[0] = 2.f * (d0 + d1); Dp[1] = Dp[0] + 2.f * d2; Dp[2] = 2.f * (d1 + d2);
            float ii[3], u1s[3];
            float is = -1.0f;
            #pragma unroll
            for (int k = 0; k < 3; k++) {
                float i  = __fdividef(1.0f, fmaf(AL, D[k], 1.0f));
                float i2 = i * i, i3 = i2 * i, i4 = i2 * i2;
                float u1 = AL * Dp[k];
                float gp = -2.0f * u1 * i3;
                float h2 = fmaf(3.0f * u1 * u1, i4, -AL * Dpp[k] * i3);
                float T0 = fmaf(M2, h2, fmaf(M1, gp, M0 * i2));
                acc[k]     += T0;
                acc[3 + k] += fmaf(fc, T0, fmaf(M2, gp, M1 * i2));
                ii[k] = i; u1s[k] = u1;
                is += i;
            }
            isv[q] = is;

            if (chk) {
                float e0 = fc - v0, e1 = fc - v1, e2 = fc - v2;
                float c0 = e0 * e0, c1 = e1 * e1, c2 = e2 * e2;
                float Dv[3], Dvp[3];
                Dv[0] = c0 + c1 + TAU2F; Dv[1] = Dv[0] + c2; Dv[2] = c1 + c2 + TAU2F;
                Dvp[0] = 2.f * (e0 + e1); Dvp[1] = Dvp[0] + 2.f * e2; Dvp[2] = 2.f * (e1 + e2);
                #pragma unroll
                for (int k = 0; k < 3; k++) {
                    float iv  = __fdividef(1.0f, fmaf(AL, Dv[k], 1.0f));
                    float iv2 = iv * iv, iv3 = iv2 * iv;
                    float u1v = AL * Dvp[k];
                    float ivp  = -u1v * iv2;
                    float ivpp = fmaf(2.0f * u1v * u1v, iv3, -AL * Dpp[k] * iv2);
                    float i  = ii[k], u1 = u1s[k];
                    float i2 = i * i, i3 = i2 * i;
                    float ip  = -u1 * i2;
                    float ipp = fmaf(2.0f * u1 * u1, i3, -AL * Dpp[k] * i2);
                    float dI = i - iv, dIp = ip - ivp, dIpp = ipp - ivpp;
                    acc[6] += fmaf(M0, dI * dI,
                               fmaf(M1, 2.0f * dI * dIp,
                                    M2 * fmaf(dIp, dIp, dI * dIpp)));
                    acc[7] += fmaf(M0, iv2,
                               fmaf(M1, 2.0f * iv * ivp,
                                    M2 * fmaf(ivp, ivp, iv * ivpp)));
                }
            }
        }

        // warp shfl reduce (8 comps), lane0 -> sred[warp][a]
        #pragma unroll
        for (int a = 0; a < 8; a++) {
            float v = acc[a];
            #pragma unroll
            for (int o = 16; o; o >>= 1) v += __shfl_down_sync(0xffffffffu, v, o);
            if (lane == 0) sred[warp][a] = v;
        }
        __syncthreads();

        // warp 0: 32 lanes hold sred[w][a] (w=lane>>3, a=lane&7); fp64 tree
        if (warp == 0) {
            double d = (double)sred[lane >> 3][lane & 7];
            d += __shfl_down_sync(0xffffffffu, d, 16);
            d += __shfl_down_sync(0xffffffffu, d, 8);      // lanes 0..7 = S[a]
            double S[8];
            #pragma unroll
            for (int a = 0; a < 8; a++)
                S[a] = __shfl_sync(0xffffffffu, d, a);
            if (lane == 0) {
                float wn0 = (float)S[3] / (float)S[0];
                float wn1 = (float)S[4] / (float)S[1];
                float wn2 = (float)S[5] / (float)S[2];
                float convf = 0.f;
                if (chk) {
                    double udiff = S[6] / S[7];
                    double omd = (fabs((double)wn0 - (double)wn2) +
                                  fabs((double)wn1 - (double)wn0) +
                                  fabs((double)wn2 - (double)wn1)) * (1.0 / 3.0);
                    if (udiff < TOL_C && omd < TOL_C) convf = 1.f;
                }
                sw[0] = wn0; sw[1] = wn1; sw[2] = wn2; sw[3] = convf;
            }
        }
        __syncthreads();

        float nw0 = sw[0], nw1 = sw[1], nw2 = sw[2], cf = sw[3];
        __syncthreads();                 // protect sw before next iteration
        if (cf != 0.f) break;            // frozen: keep w (entering), Csum as-is
        #pragma unroll
        for (int q = 0; q < BPT; q++) Csum[q] += isv[q];
        v0 = w0; v1 = w1; v2 = w2;
        w0 = nw0; w1 = nw1; w2 = nw2;
    }

    if (tix == 0) {
        g_omega_out[0] = w0; g_omega_out[1] = w1; g_omega_out[2] = w2;
    }
    #pragma unroll
    for (int q = 0; q < BPT; q++)
        g_csum[tix * BPT + q] = TAU_C * Csum[q];
}

// ---------------------------------------------------------------------------

extern "C" void kernel_launch(void* const* d_in, const int* in_sizes, int n_in,
                              void* d_out, int out_size) {
    const float* x       = (const float*)d_in[0];
    const float* om_init = (const float*)d_in[1];
    float* out = (float*)d_out;

    cudaFuncSetAttribute(fft_pass1<0>, cudaFuncAttributeMaxDynamicSharedMemorySize, SMEM_FFT);
    cudaFuncSetAttribute(fft_pass1<1>, cudaFuncAttributeMaxDynamicSharedMemorySize, SMEM_FFT);
    cudaFuncSetAttribute(fft_pass2<0>, cudaFuncAttributeMaxDynamicSharedMemorySize, SMEM_FFT);
    cudaFuncSetAttribute(fft_pass2<1>, cudaFuncAttributeMaxDynamicSharedMemorySize, SMEM_FFT);

    float2* buf;
    cudaGetSymbolAddress((void**)&buf, g_buf);
    float2* F  = buf;                       // [0, T)
    float2* wk = buf + (size_t)TSIG;        // FFT work region (3T)

    // Forward FFT of x -> F
    fft_pass1<0><<<dim3(256, 1), 256, SMEM_FFT>>>(x, wk);
    fft_pass2<0><<<dim3(256, 1), 256, SMEM_FFT>>>(wk, F, nullptr);

    // Binned moments of |F|^2, then the whole omega fixed point in one block
    bin_moments<<<NBINS, 256>>>();
    vmd_omega<<<1, OTPB>>>(om_init);

    // inverse: pass1 builds conj(u_hat) from closed form, then Re(fft(conj(u)))/T
    fft_pass1<1><<<dim3(256, 3), 256, SMEM_FFT>>>(nullptr, wk);
    fft_pass2<1><<<dim3(256, 3), 256, SMEM_FFT>>>(wk, nullptr, out);
}